// round 12
// baseline (speedup 1.0000x reference)
#include <cuda_runtime.h>
#include <cuda_bf16.h>
#include <math.h>
#include <float.h>
#include <cub/block/block_radix_sort.cuh>

#define NN   16384
#define PER  512
#define NGR  32
#define EE   262144
#define CAP  16384      // per-graph edge capacity (2^14)
#define CAPB 14
#define FMAX 600
#define FINMAX 400

// ----------------------------- scratch (device globals) -----------------------
__device__ float g_X[NN * FMAX];     // level input features / pooled output
__device__ float g_Y[NN * FINMAX];   // aggregated input features (pre-GEMM)
__device__ float g_C[NN * FMAX];     // conv output
__device__ float g_na[NN], g_nb[NN];
__device__ float g_dinv[NN], g_cself[NN];
__device__ int   g_cluster[NN];
__device__ int   g_partner[2 * NN];  // double-buffered per level
__device__ float g_nscore[2 * NN];   // double-buffered per level
__device__ unsigned char g_nvalid[NN];
__device__ int   g_rs[NN], g_re[NN];        // CSR row range in dst-sorted order
__device__ int   g_rowmap[NN];              // per-graph compacted valid-node list
__device__ int   g_vcnt[NGR];               // valid-node count per graph

__device__ int g_srcA[NGR * CAP], g_dstA[NGR * CAP];
__device__ int g_srcB[NGR * CAP], g_dstB[NGR * CAP];
__device__ int g_cntA[NGR] = {};            // zero-init; reset at end of each call
__device__ int g_cntB[NGR];
__device__ int g_eidx[NGR * CAP];           // stable-tie index (orig order), by slot
__device__ int g_sslot[NGR * CAP];          // dst-sorted rank -> slot
__device__ int g_ssrc[NGR * CAP];           // dst-sorted rank -> global src node
__device__ float g_escore[NGR * CAP];       // by slot
__device__ unsigned long long g_ukey[NGR * CAP];  // by slot: (score desc, idx asc)
__device__ float g_pool[NGR * FMAX];

// ----------------------------- helpers ---------------------------------------
__device__ __forceinline__ unsigned enc_f(float f) {
    unsigned u = __float_as_uint(f);
    return (u & 0x80000000u) ? ~u : (u | 0x80000000u);
}
__device__ __forceinline__ unsigned long long pack2(float x, float y) {
    unsigned long long r;
    asm("mov.b64 %0, {%1, %2};" : "=l"(r) : "f"(x), "f"(y));
    return r;
}
__device__ __forceinline__ void unpack2(float& x, float& y, unsigned long long v) {
    asm("mov.b64 {%0, %1}, %2;" : "=f"(x), "=f"(y) : "l"(v));
}
__device__ __forceinline__ unsigned long long fma2(unsigned long long a,
                                                   unsigned long long b,
                                                   unsigned long long c) {
    unsigned long long d;
    asm("fma.rn.f32x2 %0, %1, %2, %3;" : "=l"(d) : "l"(a), "l"(b), "l"(c));
    return d;
}

// ----------------------------- ingest (+ per-call node init) -------------------
__global__ void k_ingest(const int* __restrict__ ei) {
    int e = blockIdx.x * blockDim.x + threadIdx.x;
    if (e < NN) { g_nvalid[e] = 1; g_rowmap[e] = e; }
    if (e < NGR) g_vcnt[e] = PER;
    if (e >= EE) return;
    int s = ei[e], d = ei[EE + e];
    int g = s >> 9;
    int pos = atomicAdd(&g_cntA[g], 1);     // cntA zeroed at end of previous call
    if (pos < CAP) {
        g_srcA[g * CAP + pos] = s;
        g_dstA[g * CAP + pos] = d;
        g_eidx[g * CAP + pos] = e;
    }
}

// ----------------------------- sorts ------------------------------------------
constexpr int SORT_T = 512;
constexpr int SORT_I = 32;
using SortT64 = cub::BlockRadixSort<unsigned long long, SORT_T, SORT_I>;
using SortT32 = cub::BlockRadixSort<unsigned, SORT_T, SORT_I>;

// level-1 dst-sort + CSR + node init (resets buffer 0)
__global__ void __launch_bounds__(SORT_T, 1) k_sortdst() {
    extern __shared__ char smraw[];
    const int* src = g_srcA;
    const int* dst = g_dstA;
    int g = blockIdx.x, base = g * CAP, t = threadIdx.x;
    int cnt = g_cntA[g]; if (cnt > CAP) cnt = CAP;

    unsigned keys[SORT_I];
#pragma unroll
    for (int i = 0; i < SORT_I; i++) {
        int slot = t * SORT_I + i;
        if (slot < cnt) {
            unsigned d = (unsigned)(dst[base + slot] & (PER - 1));
            keys[i] = (d << CAPB) | (unsigned)slot;
        } else {
            keys[i] = (512u << CAPB) | (unsigned)slot;
        }
    }
    {
        typename SortT32::TempStorage& temp =
            *reinterpret_cast<typename SortT32::TempStorage*>(smraw);
        SortT32(temp).Sort(keys, CAPB, 24);
    }
    __syncthreads();
    unsigned short* d16 = (unsigned short*)smraw;
#pragma unroll
    for (int i = 0; i < SORT_I; i++) {
        int r = t * SORT_I + i;
        unsigned k = keys[i];
        int slot = (int)(k & (CAP - 1));
        int d = (int)(k >> CAPB);
        if (r < cnt) {
            g_sslot[base + r] = slot;
            g_ssrc[base + r] = src[base + slot];
            d16[r] = (unsigned short)d;
        }
    }
    __syncthreads();
    if (t < PER) { g_rs[g * PER + t] = 0; g_re[g * PER + t] = 0; }
    __syncthreads();
    for (int r = t; r < cnt; r += SORT_T) {
        int d = d16[r];
        if (r == 0 || d16[r - 1] != d) g_rs[g * PER + d] = r;
        if (r == cnt - 1 || d16[r + 1] != d) g_re[g * PER + d] = r + 1;
    }
    __syncthreads();
    {
        int nid = g * PER + t;
        int rs = g_rs[nid], re = g_re[nid];
        int selfv = 0;
        for (int r = rs; r < re; r++)
            if (g_ssrc[base + r] == nid) selfv = 1;
        float add = selfv ? 0.f : 1.f;
        float td = (float)(re - rs) + add;
        g_dinv[nid] = rsqrtf(td);
        g_cself[nid] = add / td;
        g_cluster[nid] = nid;
        g_nscore[nid] = 1.f;        // buf 0
        g_partner[nid] = -1;        // buf 0
        g_na[nid] = 0.f;
        g_nb[nid] = 0.f;
    }
}

// Fused coalesce + dst-sort + CSR + node init for the NEXT level.
// Resets nscore/partner in `nextbuf` (the buffer the next level will use).
__global__ void __launch_bounds__(SORT_T, 1) k_coalsort(int inA, int nextbuf) {
    extern __shared__ char smraw[];
    __shared__ int s_cnt2;
    int g = blockIdx.x, base = g * CAP, t = threadIdx.x;
    const int* src = inA ? g_srcA : g_srcB;
    const int* dst = inA ? g_dstA : g_dstB;
    const int* cntp = inA ? g_cntA : g_cntB;
    int* osrc = inA ? g_srcB : g_srcA;
    int* odst = inA ? g_dstB : g_dstA;
    int* ocnt = inA ? g_cntB : g_cntA;
    int cnt = cntp[g]; if (cnt > CAP) cnt = CAP;

    // ---- phase 1: remap + dedupe (src-major sorted, matching jnp.argsort of ekey)
    unsigned long long keys[SORT_I];
#pragma unroll
    for (int i = 0; i < SORT_I; i++) {
        int slot = t * SORT_I + i;
        if (slot < cnt) {
            int ns = g_cluster[src[base + slot]] & (PER - 1);
            int nd = g_cluster[dst[base + slot]] & (PER - 1);
            keys[i] = ((unsigned long long)(unsigned)((ns << 9) | nd) << CAPB) | (unsigned)slot;
        } else keys[i] = (1ull << 32);
    }
    {
        typename SortT64::TempStorage& temp =
            *reinterpret_cast<typename SortT64::TempStorage*>(smraw);
        SortT64(temp).Sort(keys, CAPB, 33);
    }
    __syncthreads();
    unsigned long long* lastk = (unsigned long long*)smraw;          // SORT_T
    int* scan = (int*)(smraw + SORT_T * sizeof(unsigned long long)); // SORT_T
    lastk[t] = keys[SORT_I - 1];
    __syncthreads();
    unsigned prevl = (t == 0) ? 0xFFFFFFFFu : (unsigned)(lastk[t - 1] >> CAPB);
    int flags[SORT_I]; int cl = 0;
#pragma unroll
    for (int i = 0; i < SORT_I; i++) {
        int r = t * SORT_I + i;
        unsigned lk = (unsigned)(keys[i] >> CAPB);
        bool f = (r < cnt) && (lk != prevl);
        flags[i] = f; cl += f; prevl = lk;
    }
    __syncthreads();
    scan[t] = cl;
    __syncthreads();
    for (int off = 1; off < SORT_T; off <<= 1) {
        int v = (t >= off) ? scan[t - off] : 0;
        __syncthreads();
        scan[t] += v;
        __syncthreads();
    }
    int pos = scan[t] - cl;
#pragma unroll
    for (int i = 0; i < SORT_I; i++) {
        if (flags[i]) {
            unsigned lk = (unsigned)(keys[i] >> CAPB);
            osrc[base + pos] = g * PER + ((lk >> 9) & 511);
            odst[base + pos] = g * PER + (lk & 511);
            g_eidx[base + pos] = pos;
            pos++;
        }
    }
    if (t == SORT_T - 1) s_cnt2 = scan[t];
    __syncthreads();
    int cnt2 = s_cnt2;
    if (t == 0) ocnt[g] = cnt2;
    __syncthreads();   // osrc/odst visible to CTA

    // ---- phase 2: dst-sort of the new edges + CSR + node init
    unsigned k2[SORT_I];
#pragma unroll
    for (int i = 0; i < SORT_I; i++) {
        int slot = t * SORT_I + i;
        if (slot < cnt2) {
            unsigned d = (unsigned)(odst[base + slot] & (PER - 1));
            k2[i] = (d << CAPB) | (unsigned)slot;
        } else {
            k2[i] = (512u << CAPB) | (unsigned)slot;
        }
    }
    {
        typename SortT32::TempStorage& temp =
            *reinterpret_cast<typename SortT32::TempStorage*>(smraw);
        SortT32(temp).Sort(k2, CAPB, 24);
    }
    __syncthreads();
    unsigned short* d16 = (unsigned short*)smraw;
#pragma unroll
    for (int i = 0; i < SORT_I; i++) {
        int r = t * SORT_I + i;
        unsigned k = k2[i];
        int slot = (int)(k & (CAP - 1));
        int d = (int)(k >> CAPB);
        if (r < cnt2) {
            g_sslot[base + r] = slot;
            g_ssrc[base + r] = osrc[base + slot];
            d16[r] = (unsigned short)d;
        }
    }
    __syncthreads();
    if (t < PER) { g_rs[g * PER + t] = 0; g_re[g * PER + t] = 0; }
    __syncthreads();
    for (int r = t; r < cnt2; r += SORT_T) {
        int d = d16[r];
        if (r == 0 || d16[r - 1] != d) g_rs[g * PER + d] = r;
        if (r == cnt2 - 1 || d16[r + 1] != d) g_re[g * PER + d] = r + 1;
    }
    __syncthreads();
    {
        int nid = g * PER + t;
        int rs = g_rs[nid], re = g_re[nid];
        int selfv = 0;
        for (int r = rs; r < re; r++)
            if (g_ssrc[base + r] == nid) selfv = 1;
        float add = selfv ? 0.f : 1.f;
        float td = (float)(re - rs) + add;
        g_dinv[nid] = rsqrtf(td);
        g_cself[nid] = add / td;
        g_cluster[nid] = nid;
        g_nscore[nextbuf * NN + nid] = 1.f;
        g_partner[nextbuf * NN + nid] = -1;
        g_na[nid] = 0.f;
        g_nb[nid] = 0.f;
    }
}

// CSR aggregation over INPUT features: y = cself*x + dinv[d]*sum(dinv[s]*x[s])
__global__ void k_aggY(int F, const float* __restrict__ Xp) {
    const float* X = Xp ? Xp : g_X;
    int g = blockIdx.y;
    int lane = threadIdx.x & 31;
    int w = threadIdx.x >> 5;
    int d = blockIdx.z * 8 + w;
    int f = blockIdx.x * 32 + lane;
    bool fv = (f < F);
    int nid = g * PER + d;
    int base = g * CAP;
    int rs = g_rs[nid], re = g_re[nid];
    float acc = 0.f;
    int r = rs;
    for (; r + 4 <= re; r += 4) {
        int s0 = g_ssrc[base + r];
        int s1 = g_ssrc[base + r + 1];
        int s2 = g_ssrc[base + r + 2];
        int s3 = g_ssrc[base + r + 3];
        float v0 = fv ? X[s0 * F + f] : 0.f;
        float v1 = fv ? X[s1 * F + f] : 0.f;
        float v2 = fv ? X[s2 * F + f] : 0.f;
        float v3 = fv ? X[s3 * F + f] : 0.f;
        acc += g_dinv[s0] * v0 + g_dinv[s1] * v1
             + g_dinv[s2] * v2 + g_dinv[s3] * v3;
    }
    for (; r < re; r++) {
        int s = g_ssrc[base + r];
        acc += g_dinv[s] * (fv ? X[s * F + f] : 0.f);
    }
    if (fv && g_nvalid[nid])
        g_Y[nid * F + f] = g_cself[nid] * X[nid * F + f] + acc * g_dinv[nid];
}

// GEMM C = Y @ W + bias over COMPACTED valid rows; 128x64 tile, 8x4 microtile.
// grid: (ceil(Nc/64), 4 row-tiles of 128, NGR graphs)
__global__ void __launch_bounds__(256, 2) k_gemm(
        int K, int Nc, const float* __restrict__ W,
        const float* __restrict__ bias, const float* __restrict__ Pw,
        const float* __restrict__ Ap) {
    const float* A = Ap ? Ap : g_Y;
    int g = blockIdx.z;
    int bmL = blockIdx.y * 128;
    if (bmL >= g_vcnt[g]) return;
    __shared__ __align__(16) float As[2][16][140];
    __shared__ __align__(16) float Bs[2][16][68];
    int t = threadIdx.x;
    int bn = blockIdx.x * 64;
    int tm = (t >> 4) << 3, tn = (t & 15) << 2;
    int nidA[8], nidE[8];
#pragma unroll
    for (int i = 0; i < 8; i++) {
        nidA[i] = g_rowmap[g * PER + bmL + ((t + i * 256) >> 4)];
        nidE[i] = g_rowmap[g * PER + bmL + tm + i];
    }
    unsigned long long acc2[8][2];
#pragma unroll
    for (int i = 0; i < 8; i++) { acc2[i][0] = pack2(0.f, 0.f); acc2[i][1] = pack2(0.f, 0.f); }

    int nslices = (K + 15) / 16;
#pragma unroll
    for (int i = 0; i < 8; i++) {
        int lin = t + i * 256;
        int m = lin >> 4, kk = lin & 15;
        As[0][kk][m] = (nidA[i] >= 0 && kk < K) ? A[nidA[i] * K + kk] : 0.f;
    }
#pragma unroll
    for (int i = 0; i < 4; i++) {
        int lin = t + i * 256;
        int k2 = lin >> 6, n2 = lin & 63;
        Bs[0][k2][n2] = (k2 < K && bn + n2 < Nc) ? W[k2 * Nc + bn + n2] : 0.f;
    }
    __syncthreads();
    int buf = 0;
    for (int sI = 0; sI < nslices; sI++) {
        if (sI + 1 < nslices) {
            int k0 = (sI + 1) * 16, nb = buf ^ 1;
#pragma unroll
            for (int i = 0; i < 8; i++) {
                int lin = t + i * 256;
                int m = lin >> 4, kk = lin & 15;
                As[nb][kk][m] = (nidA[i] >= 0 && k0 + kk < K) ? A[nidA[i] * K + k0 + kk] : 0.f;
            }
#pragma unroll
            for (int i = 0; i < 4; i++) {
                int lin = t + i * 256;
                int k2 = lin >> 6, n2 = lin & 63;
                Bs[nb][k2][n2] = (k0 + k2 < K && bn + n2 < Nc)
                                 ? W[(k0 + k2) * Nc + bn + n2] : 0.f;
            }
        }
#pragma unroll
        for (int kk = 0; kk < 16; kk++) {
            float4 a0 = *(const float4*)&As[buf][kk][tm];
            float4 a1 = *(const float4*)&As[buf][kk][tm + 4];
            ulonglong2 bb = *(const ulonglong2*)&Bs[buf][kk][tn];
            float av[8] = {a0.x, a0.y, a0.z, a0.w, a1.x, a1.y, a1.z, a1.w};
#pragma unroll
            for (int i = 0; i < 8; i++) {
                unsigned long long ap = pack2(av[i], av[i]);
                acc2[i][0] = fma2(ap, bb.x, acc2[i][0]);
                acc2[i][1] = fma2(ap, bb.y, acc2[i][1]);
            }
        }
        __syncthreads();
        buf ^= 1;
    }
#pragma unroll
    for (int i = 0; i < 8; i++) {
        float pa = 0.f, pb = 0.f;
        if (nidE[i] >= 0) {
            float v0, v1, v2, v3;
            unpack2(v0, v1, acc2[i][0]);
            unpack2(v2, v3, acc2[i][1]);
            float vv[4] = {v0, v1, v2, v3};
#pragma unroll
            for (int j = 0; j < 4; j++) {
                int col = bn + tn + j;
                if (col < Nc) {
                    float c = vv[j] + bias[col];
                    g_C[nidE[i] * Nc + col] = c;
                    pa += c * Pw[col];
                    pb += c * Pw[Nc + col];
                }
            }
        }
        for (int o = 8; o > 0; o >>= 1) {
            pa += __shfl_down_sync(0xFFFFFFFFu, pa, o, 16);
            pb += __shfl_down_sync(0xFFFFFFFFu, pb, o, 16);
        }
        if ((t & 15) == 0 && nidE[i] >= 0) {
            atomicAdd(&g_na[nidE[i]], pa);
            atomicAdd(&g_nb[nidE[i]], pb);
        }
    }
}

// per-dst softmax: warp per node, shuffle reductions
__global__ void k_maxden(const float* __restrict__ Pb) {
    int gt = blockIdx.x * blockDim.x + threadIdx.x;
    int node = gt >> 5, lane = gt & 31;
    if (node >= NN) return;
    int g = node >> 9, base = g * CAP;
    int rs = g_rs[node], re = g_re[node];
    if (rs >= re) return;
    float nbd = g_nb[node] + Pb[0];
    float mx = -FLT_MAX;
    for (int r = rs + lane; r < re; r += 32)
        mx = fmaxf(mx, g_na[g_ssrc[base + r]] + nbd);
    for (int o = 16; o > 0; o >>= 1)
        mx = fmaxf(mx, __shfl_xor_sync(0xFFFFFFFFu, mx, o));
    float den = 0.f;
    for (int r = rs + lane; r < re; r += 32)
        den += expf(g_na[g_ssrc[base + r]] + nbd - mx);
    for (int o = 16; o > 0; o >>= 1)
        den += __shfl_xor_sync(0xFFFFFFFFu, den, o);
    den = fmaxf(den, 1e-16f);
    for (int r = rs + lane; r < re; r += 32) {
        float ex = expf(g_na[g_ssrc[base + r]] + nbd - mx);
        float sc = ex / den + 0.1f;
        int slot = g_sslot[base + r];
        g_escore[base + slot] = sc;
        g_ukey[base + slot] = ((unsigned long long)enc_f(sc) << 18)
                            | (unsigned)(0x3FFFFu - (unsigned)g_eidx[base + slot]);
    }
}

// ----------------------------- locally-dominant greedy matching ----------------
static const size_t MATCH_SMEM = (size_t)CAP * 4 + PER * 8 + (size_t)CAP * 4 + PER + 32;

__global__ void __launch_bounds__(SORT_T, 1) k_matchdom(int inA, int buf) {
    extern __shared__ char sm[];
    __shared__ int wsum[16];
    unsigned* pairs = (unsigned*)sm;                                        // CAP u32
    unsigned long long* best = (unsigned long long*)(sm + (size_t)CAP * 4); // PER u64
    unsigned short* lst0 = (unsigned short*)(sm + (size_t)CAP * 4 + PER * 8);
    unsigned short* lst1 = lst0 + CAP;
    unsigned char* marked = (unsigned char*)(sm + (size_t)CAP * 4 + PER * 8 + (size_t)CAP * 4);
    int* cntr = (int*)(sm + (size_t)CAP * 4 + PER * 8 + (size_t)CAP * 4 + PER);
    const int* src = inA ? g_srcA : g_srcB;
    const int* dst = inA ? g_dstA : g_dstB;
    const int* cntp = inA ? g_cntA : g_cntB;
    int g = blockIdx.x, base = g * CAP, t = threadIdx.x;
    int cnt = cntp[g]; if (cnt > CAP) cnt = CAP;

    for (int sl = t; sl < cnt; sl += SORT_T) {
        int s = src[base + sl] & (PER - 1);
        int d = dst[base + sl] & (PER - 1);
        pairs[sl] = (unsigned)((s << 9) | d);
        lst0[sl] = (unsigned short)sl;
    }
    for (int p = t; p < PER; p += SORT_T)
        marked[p] = g_nvalid[g * PER + p] ? 0 : 1;
    __syncthreads();

    unsigned short* cur = lst0;
    unsigned short* nxt = lst1;
    int n = cnt;
    while (true) {
        for (int p = t; p < PER; p += SORT_T) best[p] = 0ull;
        if (t == 0) cntr[0] = 0;
        __syncthreads();
        for (int i = t; i < n; i += SORT_T) {
            int sl = cur[i];
            unsigned pr = pairs[sl];
            int s = pr >> 9, d = pr & 511;
            if (marked[s] | marked[d]) continue;
            int pos = atomicAdd(&cntr[0], 1);
            nxt[pos] = (unsigned short)sl;
            unsigned long long k = g_ukey[base + sl];
            atomicMax(&best[s], k);
            if (d != s) atomicMax(&best[d], k);
        }
        __syncthreads();
        n = cntr[0];
        if (n == 0) break;
        for (int i = t; i < n; i += SORT_T) {
            int sl = nxt[i];
            unsigned pr = pairs[sl];
            int s = pr >> 9, d = pr & 511;
            unsigned long long k = g_ukey[base + sl];
            if (best[s] == k && best[d] == k) {
                marked[s] = 1; marked[d] = 1;
                int sG = src[base + sl], dG = dst[base + sl];
                int rep = min(sG, dG), oth = max(sG, dG);
                g_nscore[buf * NN + rep] = g_escore[base + sl];
                if (sG != dG) {
                    g_cluster[oth] = rep;
                    g_nvalid[oth] = 0;
                    g_partner[buf * NN + rep] = oth;
                }
            }
        }
        unsigned short* tmp = cur; cur = nxt; nxt = tmp;
        __syncthreads();
    }
    // ---- compact surviving valid nodes into g_rowmap (deterministic) ----
    __syncthreads();
    int lane = t & 31, warp = t >> 5;
    int nid = g * PER + t;
    int v = g_nvalid[nid] ? 1 : 0;
    unsigned bal = __ballot_sync(0xFFFFFFFFu, v);
    int wpos = __popc(bal & ((1u << lane) - 1u));
    if (lane == 0) wsum[warp] = __popc(bal);
    __syncthreads();
    int off = 0, tot = 0;
#pragma unroll
    for (int w2 = 0; w2 < 16; w2++) {
        if (w2 < warp) off += wsum[w2];
        tot += wsum[w2];
    }
    if (v) g_rowmap[g * PER + off + wpos] = nid;
    __syncthreads();
    if (t >= tot) g_rowmap[g * PER + t] = -1;
    if (t == 0) g_vcnt[g] = tot;
}

// ----------------------------- compacted pooling (no atomics) ------------------
__global__ void k_pool(int F, int buf) {
    int g = blockIdx.y;
    int tid = blockIdx.x * blockDim.x + threadIdx.x;
    int row = tid / F;
    if (row >= g_vcnt[g]) return;
    int f = tid - row * F;
    int i = g_rowmap[g * PER + row];
    float v = g_C[i * F + f];
    int p = g_partner[buf * NN + i];
    if (p >= 0) v += g_C[p * F + f];
    g_X[i * F + f] = fmaxf(v * g_nscore[buf * NN + i], 0.f);
}

// ----------------------------- readout ----------------------------------------
__global__ void k_maxpool() {
    int g = blockIdx.y;
    int f = blockIdx.x * 128 + threadIdx.x;
    if (blockIdx.x == 0 && threadIdx.x == 0) g_cntA[g] = 0;   // reset for next call
    if (f >= 600) return;
    float m = -FLT_MAX;
    for (int p = 0; p < PER; p++) {
        int i = g * PER + p;
        if (g_nvalid[i]) m = fmaxf(m, g_X[i * 600 + f]);
    }
    g_pool[g * 600 + f] = m;
}

__global__ void k_mlp(const float* __restrict__ L1w, const float* __restrict__ L1b,
                      const float* __restrict__ L2w, const float* __restrict__ L2b,
                      const float* __restrict__ L3w, const float* __restrict__ L3b,
                      float* __restrict__ out) {
    __shared__ float z1[200];
    __shared__ float z2[20];
    __shared__ float z3[4];
    int g = blockIdx.x, t = threadIdx.x;
    if (t < 200) {
        float a = L1b[t];
        for (int k = 0; k < 600; k++) a += g_pool[g * 600 + k] * L1w[k * 200 + t];
        z1[t] = fmaxf(a, 0.f);
    }
    __syncthreads();
    if (t < 20) {
        float a = L2b[t];
        for (int k = 0; k < 200; k++) a += z1[k] * L2w[k * 20 + t];
        z2[t] = fmaxf(a, 0.f);
    }
    __syncthreads();
    if (t < 4) {
        float a = L3b[t];
        for (int k = 0; k < 20; k++) a += z2[k] * L3w[k * 4 + t];
        z3[t] = fmaxf(a, 0.f);
    }
    __syncthreads();
    if (t == 0) {
        float m = fmaxf(fmaxf(z3[0], z3[1]), fmaxf(z3[2], z3[3]));
        float e0 = expf(z3[0] - m), e1 = expf(z3[1] - m);
        float e2 = expf(z3[2] - m), e3 = expf(z3[3] - m);
        float s = e0 + e1 + e2 + e3;
        out[g * 4 + 0] = e0 / s;
        out[g * 4 + 1] = e1 / s;
        out[g * 4 + 2] = e2 / s;
        out[g * 4 + 3] = e3 / s;
    }
}

// ----------------------------- host orchestration ------------------------------
extern "C" void kernel_launch(void* const* d_in, const int* in_sizes, int n_in,
                              void* d_out, int out_size) {
    (void)in_sizes; (void)n_in; (void)out_size;
    const float* x   = (const float*)d_in[0];
    const int*   ei  = (const int*)d_in[1];
    const float* W1  = (const float*)d_in[3];
    const float* b1  = (const float*)d_in[4];
    const float* W2  = (const float*)d_in[5];
    const float* b2  = (const float*)d_in[6];
    const float* W3  = (const float*)d_in[7];
    const float* b3  = (const float*)d_in[8];
    const float* P1w = (const float*)d_in[9];
    const float* P1b = (const float*)d_in[10];
    const float* P2w = (const float*)d_in[11];
    const float* P2b = (const float*)d_in[12];
    const float* P3w = (const float*)d_in[13];
    const float* P3b = (const float*)d_in[14];
    const float* L1w = (const float*)d_in[15];
    const float* L1b = (const float*)d_in[16];
    const float* L2w = (const float*)d_in[17];
    const float* L2b = (const float*)d_in[18];
    const float* L3w = (const float*)d_in[19];
    const float* L3b = (const float*)d_in[20];
    float* out = (float*)d_out;

    size_t SMEM64 = sizeof(typename SortT64::TempStorage);
    size_t SMEM_DST = sizeof(typename SortT32::TempStorage);
    if (SMEM_DST < (size_t)CAP * 2) SMEM_DST = (size_t)CAP * 2;
    size_t SMEM_CS = SMEM64 > SMEM_DST ? SMEM64 : SMEM_DST;

    static cudaStream_t s1 = nullptr;
    static cudaEvent_t e_m1, e_m2, e_c1, e_c2;
    if (!s1) {
        cudaStreamCreateWithFlags(&s1, cudaStreamNonBlocking);
        cudaEventCreateWithFlags(&e_m1, cudaEventDisableTiming);
        cudaEventCreateWithFlags(&e_m2, cudaEventDisableTiming);
        cudaEventCreateWithFlags(&e_c1, cudaEventDisableTiming);
        cudaEventCreateWithFlags(&e_c2, cudaEventDisableTiming);
        cudaFuncSetAttribute(k_coalsort, cudaFuncAttributeMaxDynamicSharedMemorySize, (int)SMEM_CS);
        cudaFuncSetAttribute(k_sortdst,  cudaFuncAttributeMaxDynamicSharedMemorySize, (int)SMEM_DST);
        cudaFuncSetAttribute(k_matchdom, cudaFuncAttributeMaxDynamicSharedMemorySize, (int)MATCH_SMEM);
    }
    cudaStream_t s0 = 0;

    // ---------------- Level 1 (edges in A, buf 0) ----------------
    k_ingest<<<EE / 256, 256, 0, s0>>>(ei);                          // launch 0
    k_sortdst<<<NGR, SORT_T, SMEM_DST, s0>>>();                      // launch 1
    k_aggY<<<dim3((107 + 31) / 32, NGR, 64), 256, 0, s0>>>(107, x);  // launch 2
    k_gemm<<<dim3((200 + 63) / 64, 4, NGR), 256, 0, s0>>>(107, 200, W1, b1, P1w, nullptr); // launch 3 (ncu)
    k_maxden<<<(NN * 32) / 256, 256, 0, s0>>>(P1b);
    k_matchdom<<<NGR, SORT_T, MATCH_SMEM, s0>>>(1, 0);
    cudaEventRecord(e_m1, s0);
    k_pool<<<dim3((PER * 200 + 255) / 256, NGR), 256, 0, s0>>>(200, 0);
    cudaStreamWaitEvent(s1, e_m1, 0);
    k_coalsort<<<NGR, SORT_T, SMEM_CS, s1>>>(1, 1);    // edges A -> B, next level CSR
    cudaEventRecord(e_c1, s1);

    // ---------------- Level 2 (edges in B, buf 1) ----------------
    cudaStreamWaitEvent(s0, e_c1, 0);
    k_aggY<<<dim3((200 + 31) / 32, NGR, 64), 256, 0, s0>>>(200, nullptr);
    k_gemm<<<dim3((400 + 63) / 64, 4, NGR), 256, 0, s0>>>(200, 400, W2, b2, P2w, nullptr);
    k_maxden<<<(NN * 32) / 256, 256, 0, s0>>>(P2b);
    k_matchdom<<<NGR, SORT_T, MATCH_SMEM, s0>>>(0, 1);
    cudaEventRecord(e_m2, s0);
    k_pool<<<dim3((PER * 400 + 255) / 256, NGR), 256, 0, s0>>>(400, 1);
    cudaStreamWaitEvent(s1, e_m2, 0);
    k_coalsort<<<NGR, SORT_T, SMEM_CS, s1>>>(0, 0);    // edges B -> A, next level CSR
    cudaEventRecord(e_c2, s1);

    // ---------------- Level 3 (edges in A, buf 0; no coalesce after) -----------
    cudaStreamWaitEvent(s0, e_c2, 0);
    k_aggY<<<dim3((400 + 31) / 32, NGR, 64), 256, 0, s0>>>(400, nullptr);
    k_gemm<<<dim3((600 + 63) / 64, 4, NGR), 256, 0, s0>>>(400, 600, W3, b3, P3w, nullptr);
    k_maxden<<<(NN * 32) / 256, 256, 0, s0>>>(P3b);
    k_matchdom<<<NGR, SORT_T, MATCH_SMEM, s0>>>(1, 0);
    k_pool<<<dim3((PER * 600 + 255) / 256, NGR), 256, 0, s0>>>(600, 0);

    k_maxpool<<<dim3(5, NGR), 128, 0, s0>>>();
    k_mlp<<<NGR, 256, 0, s0>>>(L1w, L1b, L2w, L2b, L3w, L3b, out);
}

// round 13
// speedup vs baseline: 1.0225x; 1.0225x over previous
#include <cuda_runtime.h>
#include <cuda_bf16.h>
#include <math.h>
#include <float.h>
#include <cub/block/block_radix_sort.cuh>

#define NN   16384
#define PER  512
#define NGR  32
#define EE   262144
#define CAP  16384      // per-graph edge capacity (2^14)
#define CAPB 14
#define FMAX 600
#define FINMAX 400

// ----------------------------- scratch (device globals) -----------------------
__device__ float g_X[NN * FMAX];     // level input features / pooled output
__device__ float g_Y[NN * FINMAX];   // aggregated input features (pre-GEMM)
__device__ float g_C[NN * FMAX];     // conv output
__device__ float g_na[NN], g_nb[NN];
__device__ float g_dinv[NN], g_cself[NN];
__device__ int   g_cluster[NN];
__device__ int   g_partner[NN];
__device__ float g_nscore[NN];
__device__ unsigned char g_nvalid[NN];
__device__ int   g_rs[NN], g_re[NN];        // CSR row range in dst-sorted order
__device__ int   g_rowmap[NN];              // per-graph compacted valid-node list
__device__ int   g_vcnt[NGR];               // valid-node count per graph

__device__ int g_srcA[NGR * CAP], g_dstA[NGR * CAP];
__device__ int g_srcB[NGR * CAP], g_dstB[NGR * CAP];
__device__ int g_cntA[NGR] = {};            // zero-init; reset at end of each call
__device__ int g_cntB[NGR];
__device__ int g_eidx[NGR * CAP];           // stable-tie index (orig order), by slot
__device__ int g_sslot[NGR * CAP];          // dst-sorted rank -> slot
__device__ int g_ssrc[NGR * CAP];           // dst-sorted rank -> global src node
__device__ float g_escore[NGR * CAP];       // by slot
__device__ unsigned long long g_ukey[NGR * CAP];  // by slot: (score desc, idx asc)
__device__ float g_pool[NGR * FMAX];

// ----------------------------- helpers ---------------------------------------
__device__ __forceinline__ unsigned enc_f(float f) {
    unsigned u = __float_as_uint(f);
    return (u & 0x80000000u) ? ~u : (u | 0x80000000u);
}
__device__ __forceinline__ unsigned long long pack2(float x, float y) {
    unsigned long long r;
    asm("mov.b64 %0, {%1, %2};" : "=l"(r) : "f"(x), "f"(y));
    return r;
}
__device__ __forceinline__ void unpack2(float& x, float& y, unsigned long long v) {
    asm("mov.b64 {%0, %1}, %2;" : "=f"(x), "=f"(y) : "l"(v));
}
__device__ __forceinline__ unsigned long long fma2(unsigned long long a,
                                                   unsigned long long b,
                                                   unsigned long long c) {
    unsigned long long d;
    asm("fma.rn.f32x2 %0, %1, %2, %3;" : "=l"(d) : "l"(a), "l"(b), "l"(c));
    return d;
}

// ----------------------------- ingest (+ per-call node init) -------------------
__global__ void k_ingest(const int* __restrict__ ei) {
    int e = blockIdx.x * blockDim.x + threadIdx.x;
    if (e < NN) { g_nvalid[e] = 1; g_rowmap[e] = e; }
    if (e < NGR) g_vcnt[e] = PER;
    if (e >= EE) return;
    int s = ei[e], d = ei[EE + e];
    int g = s >> 9;
    int pos = atomicAdd(&g_cntA[g], 1);     // cntA zeroed at end of previous call
    if (pos < CAP) {
        g_srcA[g * CAP + pos] = s;
        g_dstA[g * CAP + pos] = d;
        g_eidx[g * CAP + pos] = e;
    }
}

// ----------------------------- dst-sort + CSR + node init (per-graph CTA) ------
constexpr int SORT_T = 512;
constexpr int SORT_I = 32;
using SortT64 = cub::BlockRadixSort<unsigned long long, SORT_T, SORT_I>;
using SortT32 = cub::BlockRadixSort<unsigned, SORT_T, SORT_I>;

__global__ void __launch_bounds__(SORT_T, 1) k_sortdst(int inA) {
    extern __shared__ char smraw[];
    const int* src = inA ? g_srcA : g_srcB;
    const int* dst = inA ? g_dstA : g_dstB;
    const int* cntp = inA ? g_cntA : g_cntB;
    int g = blockIdx.x, base = g * CAP, t = threadIdx.x;
    int cnt = cntp[g]; if (cnt > CAP) cnt = CAP;

    unsigned keys[SORT_I];
#pragma unroll
    for (int i = 0; i < SORT_I; i++) {
        int slot = t * SORT_I + i;
        if (slot < cnt) {
            unsigned d = (unsigned)(dst[base + slot] & (PER - 1));
            keys[i] = (d << CAPB) | (unsigned)slot;
        } else {
            keys[i] = (512u << CAPB) | (unsigned)slot;
        }
    }
    {
        typename SortT32::TempStorage& temp =
            *reinterpret_cast<typename SortT32::TempStorage*>(smraw);
        SortT32(temp).Sort(keys, CAPB, 24);
    }
    __syncthreads();
    unsigned short* d16 = (unsigned short*)smraw;
#pragma unroll
    for (int i = 0; i < SORT_I; i++) {
        int r = t * SORT_I + i;
        unsigned k = keys[i];
        int slot = (int)(k & (CAP - 1));
        int d = (int)(k >> CAPB);
        if (r < cnt) {
            g_sslot[base + r] = slot;
            g_ssrc[base + r] = src[base + slot];
            d16[r] = (unsigned short)d;
        }
    }
    __syncthreads();
    if (t < PER) { g_rs[g * PER + t] = 0; g_re[g * PER + t] = 0; }
    __syncthreads();
    for (int r = t; r < cnt; r += SORT_T) {
        int d = d16[r];
        if (r == 0 || d16[r - 1] != d) g_rs[g * PER + d] = r;
        if (r == cnt - 1 || d16[r + 1] != d) g_re[g * PER + d] = r + 1;
    }
    __syncthreads();
    {
        int nid = g * PER + t;
        int rs = g_rs[nid], re = g_re[nid];
        int selfv = 0;
        for (int r = rs; r < re; r++)
            if (g_ssrc[base + r] == nid) selfv = 1;
        float add = selfv ? 0.f : 1.f;
        float td = (float)(re - rs) + add;
        g_dinv[nid] = rsqrtf(td);
        g_cself[nid] = add / td;
        g_cluster[nid] = nid;
        g_nscore[nid] = 1.f;
        g_partner[nid] = -1;
        g_na[nid] = 0.f;
        g_nb[nid] = 0.f;
    }
}

// Compacted CSR aggregation: warp per (valid dst row, 32-feature chunk).
__global__ void k_aggY(int F, const float* __restrict__ Xp) {
    const float* X = Xp ? Xp : g_X;
    int g = blockIdx.y;
    int lane = threadIdx.x & 31;
    int w = threadIdx.x >> 5;
    int row = blockIdx.z * 8 + w;                // up to 512 valid rows
    if (row >= g_vcnt[g]) return;
    int nid = g_rowmap[g * PER + row];
    int f = blockIdx.x * 32 + lane;
    bool fv = (f < F);
    int base = g * CAP;
    int rs = g_rs[nid], re = g_re[nid];
    float acc = 0.f;
    int r = rs;
    for (; r + 4 <= re; r += 4) {
        int s0 = g_ssrc[base + r];
        int s1 = g_ssrc[base + r + 1];
        int s2 = g_ssrc[base + r + 2];
        int s3 = g_ssrc[base + r + 3];
        float v0 = fv ? X[s0 * F + f] : 0.f;
        float v1 = fv ? X[s1 * F + f] : 0.f;
        float v2 = fv ? X[s2 * F + f] : 0.f;
        float v3 = fv ? X[s3 * F + f] : 0.f;
        acc += g_dinv[s0] * v0 + g_dinv[s1] * v1
             + g_dinv[s2] * v2 + g_dinv[s3] * v3;
    }
    for (; r < re; r++) {
        int s = g_ssrc[base + r];
        acc += g_dinv[s] * (fv ? X[s * F + f] : 0.f);
    }
    if (fv)
        g_Y[nid * F + f] = g_cself[nid] * X[nid * F + f] + acc * g_dinv[nid];
}

// GEMM C = Y @ W + bias over COMPACTED valid rows; 128x64 tile, 8x4 microtile.
__global__ void __launch_bounds__(256, 2) k_gemm(
        int K, int Nc, const float* __restrict__ W,
        const float* __restrict__ bias, const float* __restrict__ Pw,
        const float* __restrict__ Ap) {
    const float* A = Ap ? Ap : g_Y;
    int g = blockIdx.z;
    int bmL = blockIdx.y * 128;
    if (bmL >= g_vcnt[g]) return;
    __shared__ __align__(16) float As[2][16][140];
    __shared__ __align__(16) float Bs[2][16][68];
    int t = threadIdx.x;
    int bn = blockIdx.x * 64;
    int tm = (t >> 4) << 3, tn = (t & 15) << 2;
    int nidA[8], nidE[8];
#pragma unroll
    for (int i = 0; i < 8; i++) {
        nidA[i] = g_rowmap[g * PER + bmL + ((t + i * 256) >> 4)];
        nidE[i] = g_rowmap[g * PER + bmL + tm + i];
    }
    unsigned long long acc2[8][2];
#pragma unroll
    for (int i = 0; i < 8; i++) { acc2[i][0] = pack2(0.f, 0.f); acc2[i][1] = pack2(0.f, 0.f); }

    int nslices = (K + 15) / 16;
#pragma unroll
    for (int i = 0; i < 8; i++) {
        int lin = t + i * 256;
        int m = lin >> 4, kk = lin & 15;
        As[0][kk][m] = (nidA[i] >= 0 && kk < K) ? A[nidA[i] * K + kk] : 0.f;
    }
#pragma unroll
    for (int i = 0; i < 4; i++) {
        int lin = t + i * 256;
        int k2 = lin >> 6, n2 = lin & 63;
        Bs[0][k2][n2] = (k2 < K && bn + n2 < Nc) ? W[k2 * Nc + bn + n2] : 0.f;
    }
    __syncthreads();
    int buf = 0;
    for (int sI = 0; sI < nslices; sI++) {
        if (sI + 1 < nslices) {
            int k0 = (sI + 1) * 16, nb = buf ^ 1;
#pragma unroll
            for (int i = 0; i < 8; i++) {
                int lin = t + i * 256;
                int m = lin >> 4, kk = lin & 15;
                As[nb][kk][m] = (nidA[i] >= 0 && k0 + kk < K) ? A[nidA[i] * K + k0 + kk] : 0.f;
            }
#pragma unroll
            for (int i = 0; i < 4; i++) {
                int lin = t + i * 256;
                int k2 = lin >> 6, n2 = lin & 63;
                Bs[nb][k2][n2] = (k0 + k2 < K && bn + n2 < Nc)
                                 ? W[(k0 + k2) * Nc + bn + n2] : 0.f;
            }
        }
#pragma unroll
        for (int kk = 0; kk < 16; kk++) {
            float4 a0 = *(const float4*)&As[buf][kk][tm];
            float4 a1 = *(const float4*)&As[buf][kk][tm + 4];
            ulonglong2 bb = *(const ulonglong2*)&Bs[buf][kk][tn];
            float av[8] = {a0.x, a0.y, a0.z, a0.w, a1.x, a1.y, a1.z, a1.w};
#pragma unroll
            for (int i = 0; i < 8; i++) {
                unsigned long long ap = pack2(av[i], av[i]);
                acc2[i][0] = fma2(ap, bb.x, acc2[i][0]);
                acc2[i][1] = fma2(ap, bb.y, acc2[i][1]);
            }
        }
        __syncthreads();
        buf ^= 1;
    }
#pragma unroll
    for (int i = 0; i < 8; i++) {
        float pa = 0.f, pb = 0.f;
        if (nidE[i] >= 0) {
            float v0, v1, v2, v3;
            unpack2(v0, v1, acc2[i][0]);
            unpack2(v2, v3, acc2[i][1]);
            float vv[4] = {v0, v1, v2, v3};
#pragma unroll
            for (int j = 0; j < 4; j++) {
                int col = bn + tn + j;
                if (col < Nc) {
                    float c = vv[j] + bias[col];
                    g_C[nidE[i] * Nc + col] = c;
                    pa += c * Pw[col];
                    pb += c * Pw[Nc + col];
                }
            }
        }
        for (int o = 8; o > 0; o >>= 1) {
            pa += __shfl_down_sync(0xFFFFFFFFu, pa, o, 16);
            pb += __shfl_down_sync(0xFFFFFFFFu, pb, o, 16);
        }
        if ((t & 15) == 0 && nidE[i] >= 0) {
            atomicAdd(&g_na[nidE[i]], pa);
            atomicAdd(&g_nb[nidE[i]], pb);
        }
    }
}

// per-dst softmax: warp per node, shuffle reductions
__global__ void k_maxden(const float* __restrict__ Pb) {
    int gt = blockIdx.x * blockDim.x + threadIdx.x;
    int node = gt >> 5, lane = gt & 31;
    if (node >= NN) return;
    int g = node >> 9, base = g * CAP;
    int rs = g_rs[node], re = g_re[node];
    if (rs >= re) return;
    float nbd = g_nb[node] + Pb[0];
    float mx = -FLT_MAX;
    for (int r = rs + lane; r < re; r += 32)
        mx = fmaxf(mx, g_na[g_ssrc[base + r]] + nbd);
    for (int o = 16; o > 0; o >>= 1)
        mx = fmaxf(mx, __shfl_xor_sync(0xFFFFFFFFu, mx, o));
    float den = 0.f;
    for (int r = rs + lane; r < re; r += 32)
        den += expf(g_na[g_ssrc[base + r]] + nbd - mx);
    for (int o = 16; o > 0; o >>= 1)
        den += __shfl_xor_sync(0xFFFFFFFFu, den, o);
    den = fmaxf(den, 1e-16f);
    for (int r = rs + lane; r < re; r += 32) {
        float ex = expf(g_na[g_ssrc[base + r]] + nbd - mx);
        float sc = ex / den + 0.1f;
        int slot = g_sslot[base + r];
        g_escore[base + slot] = sc;
        g_ukey[base + slot] = ((unsigned long long)enc_f(sc) << 18)
                            | (unsigned)(0x3FFFFu - (unsigned)g_eidx[base + slot]);
    }
}

// ----------------------------- locally-dominant greedy matching ----------------
static const size_t MATCH_SMEM = (size_t)CAP * 4 + PER * 8 + (size_t)CAP * 4 + PER + 32;

__global__ void __launch_bounds__(SORT_T, 1) k_matchdom(int inA) {
    extern __shared__ char sm[];
    __shared__ int wsum[16];
    unsigned* pairs = (unsigned*)sm;                                        // CAP u32
    unsigned long long* best = (unsigned long long*)(sm + (size_t)CAP * 4); // PER u64
    unsigned short* lst0 = (unsigned short*)(sm + (size_t)CAP * 4 + PER * 8);
    unsigned short* lst1 = lst0 + CAP;
    unsigned char* marked = (unsigned char*)(sm + (size_t)CAP * 4 + PER * 8 + (size_t)CAP * 4);
    int* cntr = (int*)(sm + (size_t)CAP * 4 + PER * 8 + (size_t)CAP * 4 + PER);
    const int* src = inA ? g_srcA : g_srcB;
    const int* dst = inA ? g_dstA : g_dstB;
    const int* cntp = inA ? g_cntA : g_cntB;
    int g = blockIdx.x, base = g * CAP, t = threadIdx.x;
    int cnt = cntp[g]; if (cnt > CAP) cnt = CAP;

    for (int sl = t; sl < cnt; sl += SORT_T) {
        int s = src[base + sl] & (PER - 1);
        int d = dst[base + sl] & (PER - 1);
        pairs[sl] = (unsigned)((s << 9) | d);
        lst0[sl] = (unsigned short)sl;
    }
    for (int p = t; p < PER; p += SORT_T)
        marked[p] = g_nvalid[g * PER + p] ? 0 : 1;
    __syncthreads();

    unsigned short* cur = lst0;
    unsigned short* nxt = lst1;
    int n = cnt;
    while (true) {
        for (int p = t; p < PER; p += SORT_T) best[p] = 0ull;
        if (t == 0) cntr[0] = 0;
        __syncthreads();
        for (int i = t; i < n; i += SORT_T) {
            int sl = cur[i];
            unsigned pr = pairs[sl];
            int s = pr >> 9, d = pr & 511;
            if (marked[s] | marked[d]) continue;
            int pos = atomicAdd(&cntr[0], 1);
            nxt[pos] = (unsigned short)sl;
            unsigned long long k = g_ukey[base + sl];
            atomicMax(&best[s], k);
            if (d != s) atomicMax(&best[d], k);
        }
        __syncthreads();
        n = cntr[0];
        if (n == 0) break;
        for (int i = t; i < n; i += SORT_T) {
            int sl = nxt[i];
            unsigned pr = pairs[sl];
            int s = pr >> 9, d = pr & 511;
            unsigned long long k = g_ukey[base + sl];
            if (best[s] == k && best[d] == k) {
                marked[s] = 1; marked[d] = 1;
                int sG = src[base + sl], dG = dst[base + sl];
                int rep = min(sG, dG), oth = max(sG, dG);
                g_nscore[rep] = g_escore[base + sl];
                if (sG != dG) {
                    g_cluster[oth] = rep;
                    g_nvalid[oth] = 0;
                    g_partner[rep] = oth;
                }
            }
        }
        unsigned short* tmp = cur; cur = nxt; nxt = tmp;
        __syncthreads();
    }
    // ---- compact surviving valid nodes into g_rowmap (deterministic) ----
    __syncthreads();
    int lane = t & 31, warp = t >> 5;
    int nid = g * PER + t;
    int v = g_nvalid[nid] ? 1 : 0;
    unsigned bal = __ballot_sync(0xFFFFFFFFu, v);
    int wpos = __popc(bal & ((1u << lane) - 1u));
    if (lane == 0) wsum[warp] = __popc(bal);
    __syncthreads();
    int off = 0, tot = 0;
#pragma unroll
    for (int w2 = 0; w2 < 16; w2++) {
        if (w2 < warp) off += wsum[w2];
        tot += wsum[w2];
    }
    if (v) g_rowmap[g * PER + off + wpos] = nid;
    __syncthreads();
    if (t >= tot) g_rowmap[g * PER + t] = -1;
    if (t == 0) g_vcnt[g] = tot;
}

// ----------------------------- compacted pooling (no atomics) ------------------
__global__ void k_pool(int F) {
    int g = blockIdx.y;
    int tid = blockIdx.x * blockDim.x + threadIdx.x;
    int row = tid / F;
    if (row >= g_vcnt[g]) return;
    int f = tid - row * F;
    int i = g_rowmap[g * PER + row];
    float v = g_C[i * F + f];
    int p = g_partner[i];
    if (p >= 0) v += g_C[p * F + f];
    g_X[i * F + f] = fmaxf(v * g_nscore[i], 0.f);
}

// ----------------------------- coalesce edges to next level -------------------
__global__ void __launch_bounds__(SORT_T, 1) k_coalesce(int inA) {
    extern __shared__ char smraw[];
    int g = blockIdx.x, base = g * CAP, t = threadIdx.x;
    const int* src = inA ? g_srcA : g_srcB;
    const int* dst = inA ? g_dstA : g_dstB;
    const int* cntp = inA ? g_cntA : g_cntB;
    int* osrc = inA ? g_srcB : g_srcA;
    int* odst = inA ? g_dstB : g_dstA;
    int* ocnt = inA ? g_cntB : g_cntA;
    int cnt = cntp[g]; if (cnt > CAP) cnt = CAP;

    unsigned long long keys[SORT_I];
#pragma unroll
    for (int i = 0; i < SORT_I; i++) {
        int slot = t * SORT_I + i;
        if (slot < cnt) {
            int ns = g_cluster[src[base + slot]] & (PER - 1);
            int nd = g_cluster[dst[base + slot]] & (PER - 1);
            keys[i] = ((unsigned long long)(unsigned)((ns << 9) | nd) << CAPB) | (unsigned)slot;
        } else keys[i] = (1ull << 32);
    }
    {
        typename SortT64::TempStorage& temp =
            *reinterpret_cast<typename SortT64::TempStorage*>(smraw);
        SortT64(temp).Sort(keys, CAPB, 33);
    }
    __syncthreads();
    unsigned long long* lastk = (unsigned long long*)smraw;          // SORT_T
    int* scan = (int*)(smraw + SORT_T * sizeof(unsigned long long)); // SORT_T
    lastk[t] = keys[SORT_I - 1];
    __syncthreads();
    unsigned prevl = (t == 0) ? 0xFFFFFFFFu : (unsigned)(lastk[t - 1] >> CAPB);
    int flags[SORT_I]; int cl = 0;
#pragma unroll
    for (int i = 0; i < SORT_I; i++) {
        int r = t * SORT_I + i;
        unsigned lk = (unsigned)(keys[i] >> CAPB);
        bool f = (r < cnt) && (lk != prevl);
        flags[i] = f; cl += f; prevl = lk;
    }
    __syncthreads();
    scan[t] = cl;
    __syncthreads();
    for (int off = 1; off < SORT_T; off <<= 1) {
        int v = (t >= off) ? scan[t - off] : 0;
        __syncthreads();
        scan[t] += v;
        __syncthreads();
    }
    int pos = scan[t] - cl;
#pragma unroll
    for (int i = 0; i < SORT_I; i++) {
        if (flags[i]) {
            unsigned lk = (unsigned)(keys[i] >> CAPB);
            osrc[base + pos] = g * PER + ((lk >> 9) & 511);
            odst[base + pos] = g * PER + (lk & 511);
            g_eidx[base + pos] = pos;
            pos++;
        }
    }
    if (t == SORT_T - 1) ocnt[g] = scan[t];
}

// ----------------------------- readout ----------------------------------------
__global__ void k_maxpool() {
    int g = blockIdx.y;
    int f = blockIdx.x * 128 + threadIdx.x;
    if (blockIdx.x == 0 && threadIdx.x == 0) g_cntA[g] = 0;   // reset for next call
    if (f >= 600) return;
    float m = -FLT_MAX;
    for (int p = 0; p < PER; p++) {
        int i = g * PER + p;
        if (g_nvalid[i]) m = fmaxf(m, g_X[i * 600 + f]);
    }
    g_pool[g * 600 + f] = m;
}

__global__ void k_mlp(const float* __restrict__ L1w, const float* __restrict__ L1b,
                      const float* __restrict__ L2w, const float* __restrict__ L2b,
                      const float* __restrict__ L3w, const float* __restrict__ L3b,
                      float* __restrict__ out) {
    __shared__ float z1[200];
    __shared__ float z2[20];
    __shared__ float z3[4];
    int g = blockIdx.x, t = threadIdx.x;
    if (t < 200) {
        float a = L1b[t];
        for (int k = 0; k < 600; k++) a += g_pool[g * 600 + k] * L1w[k * 200 + t];
        z1[t] = fmaxf(a, 0.f);
    }
    __syncthreads();
    if (t < 20) {
        float a = L2b[t];
        for (int k = 0; k < 200; k++) a += z1[k] * L2w[k * 20 + t];
        z2[t] = fmaxf(a, 0.f);
    }
    __syncthreads();
    if (t < 4) {
        float a = L3b[t];
        for (int k = 0; k < 20; k++) a += z2[k] * L3w[k * 4 + t];
        z3[t] = fmaxf(a, 0.f);
    }
    __syncthreads();
    if (t == 0) {
        float m = fmaxf(fmaxf(z3[0], z3[1]), fmaxf(z3[2], z3[3]));
        float e0 = expf(z3[0] - m), e1 = expf(z3[1] - m);
        float e2 = expf(z3[2] - m), e3 = expf(z3[3] - m);
        float s = e0 + e1 + e2 + e3;
        out[g * 4 + 0] = e0 / s;
        out[g * 4 + 1] = e1 / s;
        out[g * 4 + 2] = e2 / s;
        out[g * 4 + 3] = e3 / s;
    }
}

// ----------------------------- host orchestration ------------------------------
extern "C" void kernel_launch(void* const* d_in, const int* in_sizes, int n_in,
                              void* d_out, int out_size) {
    (void)in_sizes; (void)n_in; (void)out_size;
    const float* x   = (const float*)d_in[0];
    const int*   ei  = (const int*)d_in[1];
    const float* W1  = (const float*)d_in[3];
    const float* b1  = (const float*)d_in[4];
    const float* W2  = (const float*)d_in[5];
    const float* b2  = (const float*)d_in[6];
    const float* W3  = (const float*)d_in[7];
    const float* b3  = (const float*)d_in[8];
    const float* P1w = (const float*)d_in[9];
    const float* P1b = (const float*)d_in[10];
    const float* P2w = (const float*)d_in[11];
    const float* P2b = (const float*)d_in[12];
    const float* P3w = (const float*)d_in[13];
    const float* P3b = (const float*)d_in[14];
    const float* L1w = (const float*)d_in[15];
    const float* L1b = (const float*)d_in[16];
    const float* L2w = (const float*)d_in[17];
    const float* L2b = (const float*)d_in[18];
    const float* L3w = (const float*)d_in[19];
    const float* L3b = (const float*)d_in[20];
    float* out = (float*)d_out;

    size_t SMEM64 = sizeof(typename SortT64::TempStorage);
    size_t SMEM_DST = sizeof(typename SortT32::TempStorage);
    if (SMEM_DST < (size_t)CAP * 2) SMEM_DST = (size_t)CAP * 2;

    static cudaStream_t s1 = nullptr;
    static cudaEvent_t e_sd2, e_sd3, e_m1, e_m2, e_p1, e_p2;
    if (!s1) {
        cudaStreamCreateWithFlags(&s1, cudaStreamNonBlocking);
        cudaEventCreateWithFlags(&e_sd2, cudaEventDisableTiming);
        cudaEventCreateWithFlags(&e_sd3, cudaEventDisableTiming);
        cudaEventCreateWithFlags(&e_m1, cudaEventDisableTiming);
        cudaEventCreateWithFlags(&e_m2, cudaEventDisableTiming);
        cudaEventCreateWithFlags(&e_p1, cudaEventDisableTiming);
        cudaEventCreateWithFlags(&e_p2, cudaEventDisableTiming);
        cudaFuncSetAttribute(k_coalesce, cudaFuncAttributeMaxDynamicSharedMemorySize, (int)SMEM64);
        cudaFuncSetAttribute(k_sortdst,  cudaFuncAttributeMaxDynamicSharedMemorySize, (int)SMEM_DST);
        cudaFuncSetAttribute(k_matchdom, cudaFuncAttributeMaxDynamicSharedMemorySize, (int)MATCH_SMEM);
    }
    cudaStream_t s0 = 0;

    // ---------------- Level 1 (edges in A) ----------------
    k_ingest<<<EE / 256, 256, 0, s0>>>(ei);                          // launch 0
    k_sortdst<<<NGR, SORT_T, SMEM_DST, s0>>>(1);                     // launch 1
    k_aggY<<<dim3((107 + 31) / 32, NGR, 64), 256, 0, s0>>>(107, x);  // launch 2
    k_gemm<<<dim3((200 + 63) / 64, 4, NGR), 256, 0, s0>>>(107, 200, W1, b1, P1w, nullptr); // launch 3 (ncu)
    k_maxden<<<(NN * 32) / 256, 256, 0, s0>>>(P1b);
    k_matchdom<<<NGR, SORT_T, MATCH_SMEM, s0>>>(1);
    cudaEventRecord(e_m1, s0);
    k_pool<<<dim3((PER * 200 + 255) / 256, NGR), 256, 0, s0>>>(200);
    cudaEventRecord(e_p1, s0);
    cudaStreamWaitEvent(s1, e_m1, 0);
    k_coalesce<<<NGR, SORT_T, SMEM64, s1>>>(1);                      // edges A -> B
    cudaStreamWaitEvent(s1, e_p1, 0);
    k_sortdst<<<NGR, SORT_T, SMEM_DST, s1>>>(0);                     // level-2 CSR
    cudaEventRecord(e_sd2, s1);

    // ---------------- Level 2 (edges in B) ----------------
    cudaStreamWaitEvent(s0, e_sd2, 0);
    k_aggY<<<dim3((200 + 31) / 32, NGR, 64), 256, 0, s0>>>(200, nullptr);
    k_gemm<<<dim3((400 + 63) / 64, 4, NGR), 256, 0, s0>>>(200, 400, W2, b2, P2w, nullptr);
    k_maxden<<<(NN * 32) / 256, 256, 0, s0>>>(P2b);
    k_matchdom<<<NGR, SORT_T, MATCH_SMEM, s0>>>(0);
    cudaEventRecord(e_m2, s0);
    k_pool<<<dim3((PER * 400 + 255) / 256, NGR), 256, 0, s0>>>(400);
    cudaEventRecord(e_p2, s0);
    cudaStreamWaitEvent(s1, e_m2, 0);
    k_coalesce<<<NGR, SORT_T, SMEM64, s1>>>(0);                      // edges B -> A
    cudaStreamWaitEvent(s1, e_p2, 0);
    k_sortdst<<<NGR, SORT_T, SMEM_DST, s1>>>(1);                     // level-3 CSR
    cudaEventRecord(e_sd3, s1);

    // ---------------- Level 3 (edges in A; no coalesce after) ------------------
    cudaStreamWaitEvent(s0, e_sd3, 0);
    k_aggY<<<dim3((400 + 31) / 32, NGR, 64), 256, 0, s0>>>(400, nullptr);
    k_gemm<<<dim3((600 + 63) / 64, 4, NGR), 256, 0, s0>>>(400, 600, W3, b3, P3w, nullptr);
    k_maxden<<<(NN * 32) / 256, 256, 0, s0>>>(P3b);
    k_matchdom<<<NGR, SORT_T, MATCH_SMEM, s0>>>(1);
    k_pool<<<dim3((PER * 600 + 255) / 256, NGR), 256, 0, s0>>>(600);

    k_maxpool<<<dim3(5, NGR), 128, 0, s0>>>();
    k_mlp<<<NGR, 256, 0, s0>>>(L1w, L1b, L2w, L2b, L3w, L3b, out);
}